// round 13
// baseline (speedup 1.0000x reference)
#include <cuda_runtime.h>
#include <cuda_fp16.h>
#include <cstdint>

#define NTOK   8192
#define EDIM   2048
#define NEXP   8
#define CAPACITY 2560
#define ROWS_MAX 4096
#define KC     64
#define NKC    (EDIM/KC)     // 32 K-chunks

// ---------------- device scratch (no allocs allowed) ----------------
__device__ int    g_count[NEXP];
__device__ float  g_probSum[NEXP];
__device__ int    g_tok[NEXP*NTOK];
__device__ float  g_wgt[NEXP*NTOK];
__device__ int    g_pos[NEXP*NTOK];
__device__ int    g_code[NTOK*2];
__device__ unsigned char g_drop[NEXP*NTOK];
__device__ __half g_w16[(size_t)2*NEXP*EDIM*EDIM];        // 134 MB (w1|w2 fp16)
__device__ __half g_x16[(size_t)NTOK*EDIM];               // 33 MB
__device__ __half g_h16[(size_t)NEXP*ROWS_MAX*EDIM];      // 134 MB
__device__ __half g_y16[(size_t)NEXP*ROWS_MAX*EDIM];      // 134 MB (fp16 y)

// ---------------- helpers ----------------
__device__ __forceinline__ uint32_t smem_u32(const void* p){
  uint32_t a; asm("{ .reg .u64 t; cvta.to.shared.u64 t, %1; cvt.u32.u64 %0, t; }" : "=r"(a) : "l"(p));
  return a;
}
__device__ __forceinline__ void cpa16(uint32_t dst, const void* src){
  asm volatile("cp.async.cg.shared.global [%0], [%1], 16;" :: "r"(dst), "l"(src));
}
__device__ __forceinline__ void convert_range(const float* __restrict__ w,
                                              __half* __restrict__ dst,
                                              size_t idx, size_t stride, size_t n4){
  uint2* o = reinterpret_cast<uint2*>(dst);
  const float4* s = reinterpret_cast<const float4*>(w);
  for (size_t j=idx; j<n4; j+=stride){
    float4 v = s[j];
    __half2 a = __floats2half2_rn(v.x,v.y), b = __floats2half2_rn(v.z,v.w);
    o[j] = make_uint2(*(uint32_t*)&a, *(uint32_t*)&b);
  }
}

// ---------------- init counters ----------------
__global__ void init_kernel(){
  if (threadIdx.x < NEXP){ g_count[threadIdx.x] = 0; g_probSum[threadIdx.x] = 0.f; }
}

// ---------------- fused router (blocks 0..1023) + convert w1 (blocks 1024..3071) ----------------
__global__ void router_convert_kernel(const float* __restrict__ x, const float* __restrict__ gw,
                                      const float* __restrict__ gb, const float* __restrict__ temp,
                                      const float* __restrict__ w1){
  if (blockIdx.x >= NTOK/8){
    // ---- convert w1 ----
    const size_t NW4 = (size_t)NEXP*EDIM*EDIM/4;
    size_t nb = gridDim.x - NTOK/8;
    size_t idx = (size_t)(blockIdx.x - NTOK/8)*blockDim.x + threadIdx.x;
    convert_range(w1, g_w16, idx, nb*blockDim.x, NW4);
    return;
  }
  int t = (int)((blockIdx.x*blockDim.x + threadIdx.x) >> 5);
  int lane = threadIdx.x & 31;
  const float* xr = x + (size_t)t * EDIM;
  __half* xo = g_x16 + (size_t)t * EDIM;
  float acc[8] = {0,0,0,0,0,0,0,0};
  for (int d = lane; d < EDIM; d += 32){
    float xv = xr[d];
    xo[d] = __float2half(xv);
    const float4* g4 = reinterpret_cast<const float4*>(gw + (size_t)d*NEXP);
    float4 ga = g4[0], gbv = g4[1];
    acc[0] += xv*ga.x;  acc[1] += xv*ga.y;  acc[2] += xv*ga.z;  acc[3] += xv*ga.w;
    acc[4] += xv*gbv.x; acc[5] += xv*gbv.y; acc[6] += xv*gbv.z; acc[7] += xv*gbv.w;
  }
  #pragma unroll
  for (int off=16; off; off>>=1)
    #pragma unroll
    for (int e=0;e<8;e++) acc[e] += __shfl_down_sync(0xffffffffu, acc[e], off);
  if (lane==0){
    float it = 1.0f / fabsf(temp[0]);
    float p[8]; float m = -1e30f;
    #pragma unroll
    for (int e=0;e<8;e++){ p[e] = (acc[e]+gb[e])*it; m = fmaxf(m, p[e]); }
    float s = 0.f;
    #pragma unroll
    for (int e=0;e<8;e++){ p[e] = expf(p[e]-m); s += p[e]; }
    float inv = 1.f/s;
    #pragma unroll
    for (int e=0;e<8;e++){ p[e] *= inv; atomicAdd(&g_probSum[e], p[e]); }
    int e0 = 0;
    #pragma unroll
    for (int e=1;e<8;e++) if (p[e] > p[e0]) e0 = e;
    int e1 = (e0==0) ? 1 : 0;
    #pragma unroll
    for (int e=0;e<8;e++) if (e!=e0 && p[e] > p[e1]) e1 = e;
    float rs = 1.f/(p[e0]+p[e1]);
    int s0 = atomicAdd(&g_count[e0], 1);
    g_tok[e0*NTOK+s0] = t; g_wgt[e0*NTOK+s0] = p[e0]*rs; g_pos[e0*NTOK+s0] = t*2;
    g_code[t*2+0] = e0*NTOK + s0;
    int s1 = atomicAdd(&g_count[e1], 1);
    g_tok[e1*NTOK+s1] = t; g_wgt[e1*NTOK+s1] = p[e1]*rs; g_pos[e1*NTOK+s1] = t*2+1;
    g_code[t*2+1] = e1*NTOK + s1;
  }
}

// ---------------- capacity filter + aux loss (fused) ----------------
__global__ void capacity_aux_kernel(float* __restrict__ out, int out_size){
  if (blockIdx.x == NEXP){
    if (threadIdx.x == 0){
      float sum = 0.f;
      for (int e=0;e<NEXP;e++) sum += g_probSum[e];
      float mean = sum / NEXP;
      float var = 0.f;
      for (int e=0;e<NEXP;e++){ float d = g_probSum[e]-mean; var += d*d; }
      var /= (NEXP-1);
      float cv = sqrtf(var) / (mean + 1e-10f);
      float bal = 0.f;
      for (int e=0;e<NEXP;e++)
        bal += (g_probSum[e]/(float)NTOK) * ((float)g_count[e]/(float)NTOK);
      bal *= (float)NEXP;
      if (out_size > NTOK*EDIM) out[(size_t)NTOK*EDIM] = bal + 0.01f*cv;
    }
    return;
  }
  int e = blockIdx.x;
  int cnt = g_count[e];
  if (cnt <= CAPACITY) return;
  for (int i = threadIdx.x; i < cnt; i += blockDim.x){
    float wi = g_wgt[e*NTOK+i]; int pi = g_pos[e*NTOK+i];
    int rank = 0;
    for (int j=0;j<cnt;j++){
      float wj = g_wgt[e*NTOK+j];
      if (wj > wi || (wj == wi && g_pos[e*NTOK+j] < pi)) rank++;
    }
    g_drop[e*NTOK+i] = (rank >= CAPACITY) ? 1 : 0;
  }
  __syncthreads();
  for (int i = threadIdx.x; i < cnt; i += blockDim.x)
    if (g_drop[e*NTOK+i]) g_wgt[e*NTOK+i] = 0.f;
}

// ---------------- fp16 mma.sync GEMM, 128Mx256Nx64K chunks ----------------
#define A_ST 16384
#define B_ST 32768
#define STAGE_BYTES (A_ST + B_ST)
#define NSTAGE 4
#define META_OFF (NSTAGE*STAGE_BYTES)       // 196608
#define SMEM_TOTAL (META_OFF + 768)
#define GEMM_NY (NEXP*32)                   // 256 gemm y-rows
#define CONV_NY 64                          // extra y-rows converting w2 (MODE 1 only)

template<int MODE>
__device__ __forceinline__ void load_A(
    int kt, int slot, int tid, uint32_t sbase,
    const __half* __restrict__ Xg, const int* __restrict__ stok)
{
  int k0 = kt*KC;
  uint32_t ab = sbase + slot*STAGE_BYTES;
  #pragma unroll
  for (int i=0;i<4;i++){
    int idx = tid + i*256;
    int r = idx >> 3, ko = idx & 7;
    size_t grow = (MODE==1) ? (size_t)stok[r] : (size_t)r;
    const __half* src = Xg + grow*EDIM + k0 + ko*8;
    uint32_t dst = ab + (uint32_t)(r*128 + ((ko ^ (r&7))<<4));
    cpa16(dst, src);
  }
}
template<int HALF>
__device__ __forceinline__ void load_B(
    int kt, int slot, int tid, uint32_t sbase,
    const __half* __restrict__ Wb)
{
  int k0 = kt*KC;
  uint32_t bb = sbase + slot*STAGE_BYTES + A_ST;
  #pragma unroll
  for (int i=HALF*4;i<HALF*4+4;i++){
    int idx = tid + i*256;
    int kr = idx >> 5, no = idx & 31;
    const __half* src = Wb + (size_t)(k0+kr)*EDIM + no*8;
    uint32_t dst = bb + (uint32_t)(kr*512 + ((no ^ (kr&7))<<4));
    cpa16(dst, src);
  }
}

__device__ __forceinline__ void ks_step(
    uint32_t ab, uint32_t bb, int wm, int wn, int arow_lo, int ako_hi, int ks,
    float (&c)[4][8][4])
{
  uint32_t a[4][4], b[8][2];
  #pragma unroll
  for (int mf=0; mf<4; mf++){
    int row = wm*64 + mf*16 + arow_lo;
    int ko  = ks*2 + ako_hi;
    uint32_t addr = ab + (uint32_t)(row*128 + ((ko ^ (row&7))<<4));
    asm volatile("ldmatrix.sync.aligned.m8n8.x4.shared.b16 {%0,%1,%2,%3}, [%4];"
      : "=r"(a[mf][0]),"=r"(a[mf][1]),"=r"(a[mf][2]),"=r"(a[mf][3]) : "r"(addr));
  }
  #pragma unroll
  for (int p=0; p<4; p++){
    int kr = ks*16 + arow_lo;
    int no = wn*8 + p*2 + ako_hi;
    uint32_t addr = bb + (uint32_t)(kr*512 + ((no ^ (kr&7))<<4));
    asm volatile("ldmatrix.sync.aligned.m8n8.x4.trans.shared.b16 {%0,%1,%2,%3}, [%4];"
      : "=r"(b[2*p][0]),"=r"(b[2*p][1]),"=r"(b[2*p+1][0]),"=r"(b[2*p+1][1]) : "r"(addr));
  }
  #pragma unroll
  for (int mf=0; mf<4; mf++)
    #pragma unroll
    for (int nf=0; nf<8; nf++)
      asm volatile("mma.sync.aligned.m16n8k16.row.col.f32.f16.f16.f32 "
        "{%0,%1,%2,%3}, {%4,%5,%6,%7}, {%8,%9}, {%0,%1,%2,%3};"
        : "+f"(c[mf][nf][0]), "+f"(c[mf][nf][1]), "+f"(c[mf][nf][2]), "+f"(c[mf][nf][3])
        : "r"(a[mf][0]),"r"(a[mf][1]),"r"(a[mf][2]),"r"(a[mf][3]),
          "r"(b[nf][0]),"r"(b[nf][1]));
}

// MODE1: y-rows [0,256) do GEMM1; y-rows [256,320) convert w2 (hidden in tail waves)
template<int MODE>
__global__ void __launch_bounds__(256,1) moe_gemm(
    const float* __restrict__ bias, const float* __restrict__ wconv)
{
  if (MODE==1 && blockIdx.y >= GEMM_NY){
    const size_t NW4 = (size_t)NEXP*EDIM*EDIM/4;
    size_t nb = (size_t)gridDim.x * CONV_NY;
    size_t bid = (size_t)(blockIdx.y - GEMM_NY)*gridDim.x + blockIdx.x;
    size_t idx = bid*blockDim.x + threadIdx.x;
    convert_range(wconv, g_w16 + (size_t)NEXP*EDIM*EDIM, idx, nb*blockDim.x, NW4);
    return;
  }
  int e  = blockIdx.y >> 5;
  int rb = blockIdx.y & 31;
  int cnt = g_count[e]; if (cnt > ROWS_MAX) cnt = ROWS_MAX;
  int row0 = rb * 128;
  if (row0 >= cnt) return;
  int rows = cnt - row0; if (rows > 128) rows = 128;
  int n0 = blockIdx.x * 256;

  extern __shared__ char smem[];
  uint32_t sbase = smem_u32(smem);
  int tid = threadIdx.x, warp = tid>>5, lane = tid&31;
  int* stok = (int*)(smem + META_OFF);

  if (tid < 128){
    int tkn = 0;
    if (MODE==1 && tid < rows) tkn = g_tok[e*NTOK + row0 + tid];
    stok[tid] = tkn;
  }
  __syncthreads();

  const __half* Xg = (MODE==1) ? g_x16 : (g_h16 + ((size_t)e*ROWS_MAX + row0)*EDIM);
  const __half* Wb = g_w16 + ((size_t)((MODE-1)*NEXP + e))*EDIM*EDIM + n0;

  float c[4][8][4];
  #pragma unroll
  for (int a=0;a<4;a++)
    #pragma unroll
    for (int b=0;b<8;b++)
      #pragma unroll
      for (int q=0;q<4;q++) c[a][b][q] = 0.f;

  int wm = warp & 1, wn = warp >> 1;   // 2x4 warp grid: 64(M) x 64(N) each

  #pragma unroll
  for (int p=0;p<3;p++){
    load_A<MODE>(p, p, tid, sbase, Xg, stok);
    load_B<0>(p, p, tid, sbase, Wb);
    load_B<1>(p, p, tid, sbase, Wb);
    asm volatile("cp.async.commit_group;" ::: "memory");
  }

  int arow_lo = (lane & 15);
  int ako_hi  = (lane >> 4);

  #pragma unroll 4
  for (int kt=0; kt<NKC-3; kt++){
    int slot = kt & 3;
    asm volatile("cp.async.wait_group 2;" ::: "memory");
    __syncthreads();
    uint32_t ab = sbase + slot*STAGE_BYTES;
    uint32_t bb = ab + A_ST;
    int nslot = (kt+3) & 3;
    ks_step(ab, bb, wm, wn, arow_lo, ako_hi, 0, c);
    load_A<MODE>(kt+3, nslot, tid, sbase, Xg, stok);
    ks_step(ab, bb, wm, wn, arow_lo, ako_hi, 1, c);
    load_B<0>(kt+3, nslot, tid, sbase, Wb);
    ks_step(ab, bb, wm, wn, arow_lo, ako_hi, 2, c);
    load_B<1>(kt+3, nslot, tid, sbase, Wb);
    ks_step(ab, bb, wm, wn, arow_lo, ako_hi, 3, c);
    asm volatile("cp.async.commit_group;" ::: "memory");
  }
  #pragma unroll
  for (int kt=NKC-3; kt<NKC; kt++){
    int slot = kt & 3;
    if      (kt == NKC-3) asm volatile("cp.async.wait_group 2;" ::: "memory");
    else if (kt == NKC-2) asm volatile("cp.async.wait_group 1;" ::: "memory");
    else                  asm volatile("cp.async.wait_group 0;" ::: "memory");
    __syncthreads();
    uint32_t ab = sbase + slot*STAGE_BYTES;
    uint32_t bb = ab + A_ST;
    #pragma unroll
    for (int ks=0; ks<4; ks++) ks_step(ab, bb, wm, wn, arow_lo, ako_hi, ks, c);
  }

  // ---------------- epilogue (registers -> gmem, fp16) ----------------
  int lr = lane>>2, lc = lane&3;
  const float* brow = bias + e*EDIM + n0 + wn*64;
  __half* ob = ((MODE==1) ? g_h16 : g_y16) + ((size_t)e*ROWS_MAX + row0)*EDIM + n0 + wn*64;
  #pragma unroll
  for (int nf=0; nf<8; nf++){
    int col = nf*8 + lc*2;
    float bv0 = brow[col], bv1 = brow[col+1];
    #pragma unroll
    for (int mf=0; mf<4; mf++){
      int r_ = wm*64 + mf*16 + lr;
      if (r_ < rows){
        float v0 = c[mf][nf][0]+bv0, v1 = c[mf][nf][1]+bv1;
        if (MODE==1){ v0 = fmaxf(v0,0.f); v1 = fmaxf(v1,0.f); }
        *reinterpret_cast<__half2*>(ob + (size_t)r_*EDIM + col) = __floats2half2_rn(v0, v1);
      }
      if (r_+8 < rows){
        float v0 = c[mf][nf][2]+bv0, v1 = c[mf][nf][3]+bv1;
        if (MODE==1){ v0 = fmaxf(v0,0.f); v1 = fmaxf(v1,0.f); }
        *reinterpret_cast<__half2*>(ob + (size_t)(r_+8)*EDIM + col) = __floats2half2_rn(v0, v1);
      }
    }
  }
}

// ---------------- combine: out = x + w0*y0 + w1*y1 (y in fp16) ----------------
__global__ void combine_kernel(const float* __restrict__ x, float* __restrict__ out){
  int t = blockIdx.x;
  int c1 = g_code[2*t], c2 = g_code[2*t+1];
  int s1 = c1 & (NTOK-1), s2 = c2 & (NTOK-1);
  float w1v = (s1 < ROWS_MAX) ? g_wgt[c1] : 0.f;
  float w2v = (s2 < ROWS_MAX) ? g_wgt[c2] : 0.f;
  size_t y1o = (s1 < ROWS_MAX) ? ((size_t)(c1>>13)*ROWS_MAX + s1)*EDIM : 0;
  size_t y2o = (s2 < ROWS_MAX) ? ((size_t)(c2>>13)*ROWS_MAX + s2)*EDIM : 0;
  const float4* xr = reinterpret_cast<const float4*>(x + (size_t)t*EDIM);
  const uint2* y1 = reinterpret_cast<const uint2*>(g_y16 + y1o);
  const uint2* y2 = reinterpret_cast<const uint2*>(g_y16 + y2o);
  float4* o = reinterpret_cast<float4*>(out + (size_t)t*EDIM);
  for (int j = threadIdx.x; j < EDIM/4; j += blockDim.x){
    float4 a = xr[j];
    uint2 u1 = y1[j], u2 = y2[j];
    float2 b0 = __half22float2(*reinterpret_cast<__half2*>(&u1.x));
    float2 b1 = __half22float2(*reinterpret_cast<__half2*>(&u1.y));
    float2 c0 = __half22float2(*reinterpret_cast<__half2*>(&u2.x));
    float2 c1f = __half22float2(*reinterpret_cast<__half2*>(&u2.y));
    float4 rr;
    rr.x = a.x + w1v*b0.x + w2v*c0.x;
    rr.y = a.y + w1v*b0.y + w2v*c0.y;
    rr.z = a.z + w1v*b1.x + w2v*c1f.x;
    rr.w = a.w + w1v*b1.y + w2v*c1f.y;
    o[j] = rr;
  }
}

// ---------------- launch ----------------
extern "C" void kernel_launch(void* const* d_in, const int* in_sizes, int n_in,
                              void* d_out, int out_size){
  const float* x  = (const float*)d_in[0];
  const float* gw = (const float*)d_in[1];
  const float* gb = (const float*)d_in[2];
  const float* tp = (const float*)d_in[3];
  const float* w1 = (const float*)d_in[4];
  const float* b1 = (const float*)d_in[5];
  const float* w2 = (const float*)d_in[6];
  const float* b2 = (const float*)d_in[7];
  float* out = (float*)d_out;

  cudaFuncSetAttribute(moe_gemm<1>, cudaFuncAttributeMaxDynamicSharedMemorySize, SMEM_TOTAL);
  cudaFuncSetAttribute(moe_gemm<2>, cudaFuncAttributeMaxDynamicSharedMemorySize, SMEM_TOTAL);

  init_kernel<<<1, 64>>>();                                     // idx 0
  router_convert_kernel<<<NTOK/8 + 2048, 256>>>(x, gw, gb, tp, w1); // idx 1 (router ∥ w1)
  dim3 grid1(EDIM/256, GEMM_NY + CONV_NY);
  moe_gemm<1><<<grid1, 256, SMEM_TOTAL>>>(b1, w2);              // idx 2 (gemm1 ∥ w2)
  dim3 grid2(EDIM/256, GEMM_NY);
  moe_gemm<2><<<grid2, 256, SMEM_TOTAL>>>(b2, nullptr);         // idx 3  <-- profiled
  capacity_aux_kernel<<<NEXP+1, 256>>>(out, out_size);          // idx 4
  combine_kernel<<<NTOK, 256>>>(x, out);                        // idx 5
}

// round 14
// speedup vs baseline: 1.0221x; 1.0221x over previous
#include <cuda_runtime.h>
#include <cuda_fp16.h>
#include <cstdint>

#define NTOK   8192
#define EDIM   2048
#define NEXP   8
#define CAPACITY 2560
#define ROWS_MAX 4096
#define KC     64
#define NKC    (EDIM/KC)     // 32 K-chunks

// ---------------- device scratch (no allocs allowed) ----------------
__device__ int    g_count[NEXP];
__device__ float  g_probSum[NEXP];
__device__ int    g_tok[NEXP*NTOK];
__device__ float  g_wgt[NEXP*NTOK];
__device__ int    g_pos[NEXP*NTOK];
__device__ int    g_code[NTOK*2];
__device__ unsigned char g_drop[NEXP*NTOK];
__device__ __half g_w16[(size_t)2*NEXP*EDIM*EDIM];        // 134 MB (w1|w2 fp16)
__device__ __half g_x16[(size_t)NTOK*EDIM];               // 33 MB
__device__ __half g_h16[(size_t)NEXP*ROWS_MAX*EDIM];      // 134 MB
__device__ __half g_y16[(size_t)NEXP*ROWS_MAX*EDIM];      // 134 MB (fp16 y)

// ---------------- helpers ----------------
__device__ __forceinline__ uint32_t smem_u32(const void* p){
  uint32_t a; asm("{ .reg .u64 t; cvta.to.shared.u64 t, %1; cvt.u32.u64 %0, t; }" : "=r"(a) : "l"(p));
  return a;
}
__device__ __forceinline__ void cpa16(uint32_t dst, const void* src){
  asm volatile("cp.async.cg.shared.global [%0], [%1], 16;" :: "r"(dst), "l"(src));
}

// ---------------- fp32 -> fp16 conversion of weights (+ counter init) ----------------
__global__ void convert_kernel(const float* __restrict__ w1, const float* __restrict__ w2){
  if (blockIdx.x == 0 && threadIdx.x < NEXP){
    g_count[threadIdx.x] = 0; g_probSum[threadIdx.x] = 0.f;
  }
  const size_t NW = (size_t)NEXP*EDIM*EDIM;
  size_t i = (size_t)blockIdx.x*blockDim.x + threadIdx.x;
  size_t stride = (size_t)gridDim.x*blockDim.x;
  uint2* o1 = reinterpret_cast<uint2*>(g_w16);
  uint2* o2 = reinterpret_cast<uint2*>(g_w16 + NW);
  const float4* s1 = reinterpret_cast<const float4*>(w1);
  const float4* s2 = reinterpret_cast<const float4*>(w2);
  for (size_t j=i; j<NW/4; j+=stride){
    float4 v = s1[j];
    __half2 a = __floats2half2_rn(v.x,v.y), b = __floats2half2_rn(v.z,v.w);
    o1[j] = make_uint2(*(uint32_t*)&a, *(uint32_t*)&b);
    v = s2[j];
    a = __floats2half2_rn(v.x,v.y); b = __floats2half2_rn(v.z,v.w);
    o2[j] = make_uint2(*(uint32_t*)&a, *(uint32_t*)&b);
  }
}

// ---------------- router: warp per token (also emits x16) ----------------
__global__ void router_kernel(const float* __restrict__ x, const float* __restrict__ gw,
                              const float* __restrict__ gb, const float* __restrict__ temp){
  int t = (int)((blockIdx.x*blockDim.x + threadIdx.x) >> 5);
  int lane = threadIdx.x & 31;
  if (t >= NTOK) return;
  const float* xr = x + (size_t)t * EDIM;
  __half* xo = g_x16 + (size_t)t * EDIM;
  float acc[8] = {0,0,0,0,0,0,0,0};
  for (int d = lane; d < EDIM; d += 32){
    float xv = xr[d];
    xo[d] = __float2half(xv);
    const float4* g4 = reinterpret_cast<const float4*>(gw + (size_t)d*NEXP);
    float4 ga = g4[0], gbv = g4[1];
    acc[0] += xv*ga.x;  acc[1] += xv*ga.y;  acc[2] += xv*ga.z;  acc[3] += xv*ga.w;
    acc[4] += xv*gbv.x; acc[5] += xv*gbv.y; acc[6] += xv*gbv.z; acc[7] += xv*gbv.w;
  }
  #pragma unroll
  for (int off=16; off; off>>=1)
    #pragma unroll
    for (int e=0;e<8;e++) acc[e] += __shfl_down_sync(0xffffffffu, acc[e], off);
  if (lane==0){
    float it = 1.0f / fabsf(temp[0]);
    float p[8]; float m = -1e30f;
    #pragma unroll
    for (int e=0;e<8;e++){ p[e] = (acc[e]+gb[e])*it; m = fmaxf(m, p[e]); }
    float s = 0.f;
    #pragma unroll
    for (int e=0;e<8;e++){ p[e] = expf(p[e]-m); s += p[e]; }
    float inv = 1.f/s;
    #pragma unroll
    for (int e=0;e<8;e++){ p[e] *= inv; atomicAdd(&g_probSum[e], p[e]); }
    int e0 = 0;
    #pragma unroll
    for (int e=1;e<8;e++) if (p[e] > p[e0]) e0 = e;
    int e1 = (e0==0) ? 1 : 0;
    #pragma unroll
    for (int e=0;e<8;e++) if (e!=e0 && p[e] > p[e1]) e1 = e;
    float rs = 1.f/(p[e0]+p[e1]);
    int s0 = atomicAdd(&g_count[e0], 1);
    g_tok[e0*NTOK+s0] = t; g_wgt[e0*NTOK+s0] = p[e0]*rs; g_pos[e0*NTOK+s0] = t*2;
    g_code[t*2+0] = e0*NTOK + s0;
    int s1 = atomicAdd(&g_count[e1], 1);
    g_tok[e1*NTOK+s1] = t; g_wgt[e1*NTOK+s1] = p[e1]*rs; g_pos[e1*NTOK+s1] = t*2+1;
    g_code[t*2+1] = e1*NTOK + s1;
  }
}

// ---------------- capacity filter + aux loss (fused) ----------------
__global__ void capacity_aux_kernel(float* __restrict__ out, int out_size){
  if (blockIdx.x == NEXP){
    if (threadIdx.x == 0){
      float sum = 0.f;
      for (int e=0;e<NEXP;e++) sum += g_probSum[e];
      float mean = sum / NEXP;
      float var = 0.f;
      for (int e=0;e<NEXP;e++){ float d = g_probSum[e]-mean; var += d*d; }
      var /= (NEXP-1);
      float cv = sqrtf(var) / (mean + 1e-10f);
      float bal = 0.f;
      for (int e=0;e<NEXP;e++)
        bal += (g_probSum[e]/(float)NTOK) * ((float)g_count[e]/(float)NTOK);
      bal *= (float)NEXP;
      if (out_size > NTOK*EDIM) out[(size_t)NTOK*EDIM] = bal + 0.01f*cv;
    }
    return;
  }
  int e = blockIdx.x;
  int cnt = g_count[e];
  if (cnt <= CAPACITY) return;
  for (int i = threadIdx.x; i < cnt; i += blockDim.x){
    float wi = g_wgt[e*NTOK+i]; int pi = g_pos[e*NTOK+i];
    int rank = 0;
    for (int j=0;j<cnt;j++){
      float wj = g_wgt[e*NTOK+j];
      if (wj > wi || (wj == wi && g_pos[e*NTOK+j] < pi)) rank++;
    }
    g_drop[e*NTOK+i] = (rank >= CAPACITY) ? 1 : 0;
  }
  __syncthreads();
  for (int i = threadIdx.x; i < cnt; i += blockDim.x)
    if (g_drop[e*NTOK+i]) g_wgt[e*NTOK+i] = 0.f;
}

// ---------------- fp16 mma.sync GEMM, 128Mx256Nx64K chunks ----------------
// 8 warps in a 4x2 grid: warp tile 32(M) x 128(N).
// Crossbar reads/chunk: A 16KB x2 + B 32KB x4 = 160KB (vs 176KB for 2x4 grid).
#define A_ST 16384
#define B_ST 32768
#define STAGE_BYTES (A_ST + B_ST)
#define NSTAGE 4
#define META_OFF (NSTAGE*STAGE_BYTES)       // 196608
#define SMEM_TOTAL (META_OFF + 768)

template<int MODE>
__device__ __forceinline__ void load_A(
    int kt, int slot, int tid, uint32_t sbase,
    const __half* __restrict__ Xg, const int* __restrict__ stok)
{
  int k0 = kt*KC;
  uint32_t ab = sbase + slot*STAGE_BYTES;
  #pragma unroll
  for (int i=0;i<4;i++){
    int idx = tid + i*256;
    int r = idx >> 3, ko = idx & 7;
    size_t grow = (MODE==1) ? (size_t)stok[r] : (size_t)r;
    const __half* src = Xg + grow*EDIM + k0 + ko*8;
    uint32_t dst = ab + (uint32_t)(r*128 + ((ko ^ (r&7))<<4));
    cpa16(dst, src);
  }
}
template<int HALF>
__device__ __forceinline__ void load_B(
    int kt, int slot, int tid, uint32_t sbase,
    const __half* __restrict__ Wb)
{
  int k0 = kt*KC;
  uint32_t bb = sbase + slot*STAGE_BYTES + A_ST;
  #pragma unroll
  for (int i=HALF*4;i<HALF*4+4;i++){
    int idx = tid + i*256;
    int kr = idx >> 5, no = idx & 31;
    const __half* src = Wb + (size_t)(k0+kr)*EDIM + no*8;
    uint32_t dst = bb + (uint32_t)(kr*512 + ((no ^ (kr&7))<<4));
    cpa16(dst, src);
  }
}

// one (ks, half) step: [h==0: load a frags]; load 8 nf of B; 16 HMMA
__device__ __forceinline__ void ks_half(
    uint32_t ab, uint32_t bb, int wm, int wn, int arow_lo, int ako_hi,
    int ks, int h, uint32_t (&a)[2][4], float (&c)[2][16][4])
{
  if (h == 0){
    #pragma unroll
    for (int mf=0; mf<2; mf++){
      int row = wm*32 + mf*16 + arow_lo;
      int ko  = ks*2 + ako_hi;
      uint32_t addr = ab + (uint32_t)(row*128 + ((ko ^ (row&7))<<4));
      asm volatile("ldmatrix.sync.aligned.m8n8.x4.shared.b16 {%0,%1,%2,%3}, [%4];"
        : "=r"(a[mf][0]),"=r"(a[mf][1]),"=r"(a[mf][2]),"=r"(a[mf][3]) : "r"(addr));
    }
  }
  uint32_t b[8][2];
  #pragma unroll
  for (int p=0; p<4; p++){
    int kr = ks*16 + arow_lo;
    int no = wn*16 + (h*4 + p)*2 + ako_hi;
    uint32_t addr = bb + (uint32_t)(kr*512 + ((no ^ (kr&7))<<4));
    asm volatile("ldmatrix.sync.aligned.m8n8.x4.trans.shared.b16 {%0,%1,%2,%3}, [%4];"
      : "=r"(b[2*p][0]),"=r"(b[2*p][1]),"=r"(b[2*p+1][0]),"=r"(b[2*p+1][1]) : "r"(addr));
  }
  #pragma unroll
  for (int mf=0; mf<2; mf++)
    #pragma unroll
    for (int nf=0; nf<8; nf++)
      asm volatile("mma.sync.aligned.m16n8k16.row.col.f32.f16.f16.f32 "
        "{%0,%1,%2,%3}, {%4,%5,%6,%7}, {%8,%9}, {%0,%1,%2,%3};"
        : "+f"(c[mf][h*8+nf][0]), "+f"(c[mf][h*8+nf][1]),
          "+f"(c[mf][h*8+nf][2]), "+f"(c[mf][h*8+nf][3])
        : "r"(a[mf][0]),"r"(a[mf][1]),"r"(a[mf][2]),"r"(a[mf][3]),
          "r"(b[nf][0]),"r"(b[nf][1]));
}

template<int MODE>
__global__ void __launch_bounds__(256,1) moe_gemm(
    const float* __restrict__ bias)
{
  int e  = blockIdx.y >> 5;
  int rb = blockIdx.y & 31;
  int cnt = g_count[e]; if (cnt > ROWS_MAX) cnt = ROWS_MAX;
  int row0 = rb * 128;
  if (row0 >= cnt) return;
  int rows = cnt - row0; if (rows > 128) rows = 128;
  int n0 = blockIdx.x * 256;

  extern __shared__ char smem[];
  uint32_t sbase = smem_u32(smem);
  int tid = threadIdx.x, warp = tid>>5, lane = tid&31;
  int* stok = (int*)(smem + META_OFF);

  if (tid < 128){
    int tkn = 0;
    if (MODE==1 && tid < rows) tkn = g_tok[e*NTOK + row0 + tid];
    stok[tid] = tkn;
  }
  __syncthreads();

  const __half* Xg = (MODE==1) ? g_x16 : (g_h16 + ((size_t)e*ROWS_MAX + row0)*EDIM);
  const __half* Wb = g_w16 + ((size_t)((MODE-1)*NEXP + e))*EDIM*EDIM + n0;

  float c[2][16][4];
  #pragma unroll
  for (int a=0;a<2;a++)
    #pragma unroll
    for (int b=0;b<16;b++)
      #pragma unroll
      for (int q=0;q<4;q++) c[a][b][q] = 0.f;

  int wm = warp & 3, wn = warp >> 2;   // 4x2 warp grid: 32(M) x 128(N) each

  #pragma unroll
  for (int p=0;p<3;p++){
    load_A<MODE>(p, p, tid, sbase, Xg, stok);
    load_B<0>(p, p, tid, sbase, Wb);
    load_B<1>(p, p, tid, sbase, Wb);
    asm volatile("cp.async.commit_group;" ::: "memory");
  }

  int arow_lo = (lane & 15);
  int ako_hi  = (lane >> 4);

  #pragma unroll 4
  for (int kt=0; kt<NKC-3; kt++){
    int slot = kt & 3;
    asm volatile("cp.async.wait_group 2;" ::: "memory");
    __syncthreads();
    uint32_t ab = sbase + slot*STAGE_BYTES;
    uint32_t bb = ab + A_ST;
    int nslot = (kt+3) & 3;
    uint32_t a[2][4];
    ks_half(ab, bb, wm, wn, arow_lo, ako_hi, 0, 0, a, c);
    load_A<MODE>(kt+3, nslot, tid, sbase, Xg, stok);
    ks_half(ab, bb, wm, wn, arow_lo, ako_hi, 0, 1, a, c);
    load_B<0>(kt+3, nslot, tid, sbase, Wb);
    ks_half(ab, bb, wm, wn, arow_lo, ako_hi, 1, 0, a, c);
    load_B<1>(kt+3, nslot, tid, sbase, Wb);
    ks_half(ab, bb, wm, wn, arow_lo, ako_hi, 1, 1, a, c);
    asm volatile("cp.async.commit_group;" ::: "memory");
    ks_half(ab, bb, wm, wn, arow_lo, ako_hi, 2, 0, a, c);
    ks_half(ab, bb, wm, wn, arow_lo, ako_hi, 2, 1, a, c);
    ks_half(ab, bb, wm, wn, arow_lo, ako_hi, 3, 0, a, c);
    ks_half(ab, bb, wm, wn, arow_lo, ako_hi, 3, 1, a, c);
  }
  #pragma unroll
  for (int kt=NKC-3; kt<NKC; kt++){
    int slot = kt & 3;
    if      (kt == NKC-3) asm volatile("cp.async.wait_group 2;" ::: "memory");
    else if (kt == NKC-2) asm volatile("cp.async.wait_group 1;" ::: "memory");
    else                  asm volatile("cp.async.wait_group 0;" ::: "memory");
    __syncthreads();
    uint32_t ab = sbase + slot*STAGE_BYTES;
    uint32_t bb = ab + A_ST;
    uint32_t a[2][4];
    #pragma unroll
    for (int ks=0; ks<4; ks++){
      ks_half(ab, bb, wm, wn, arow_lo, ako_hi, ks, 0, a, c);
      ks_half(ab, bb, wm, wn, arow_lo, ako_hi, ks, 1, a, c);
    }
  }

  // ---------------- epilogue (registers -> gmem, fp16) ----------------
  int lr = lane>>2, lc = lane&3;
  const float* brow = bias + e*EDIM + n0 + wn*128;
  __half* ob = ((MODE==1) ? g_h16 : g_y16) + ((size_t)e*ROWS_MAX + row0)*EDIM + n0 + wn*128;
  #pragma unroll
  for (int nf=0; nf<16; nf++){
    int col = nf*8 + lc*2;
    float bv0 = brow[col], bv1 = brow[col+1];
    #pragma unroll
    for (int mf=0; mf<2; mf++){
      int r_ = wm*32 + mf*16 + lr;
      if (r_ < rows){
        float v0 = c[mf][nf][0]+bv0, v1 = c[mf][nf][1]+bv1;
        if (MODE==1){ v0 = fmaxf(v0,0.f); v1 = fmaxf(v1,0.f); }
        *reinterpret_cast<__half2*>(ob + (size_t)r_*EDIM + col) = __floats2half2_rn(v0, v1);
      }
      if (r_+8 < rows){
        float v0 = c[mf][nf][2]+bv0, v1 = c[mf][nf][3]+bv1;
        if (MODE==1){ v0 = fmaxf(v0,0.f); v1 = fmaxf(v1,0.f); }
        *reinterpret_cast<__half2*>(ob + (size_t)(r_+8)*EDIM + col) = __floats2half2_rn(v0, v1);
      }
    }
  }
}

// ---------------- combine: out = x + w0*y0 + w1*y1 (y in fp16) ----------------
__global__ void combine_kernel(const float* __restrict__ x, float* __restrict__ out){
  int t = blockIdx.x;
  int c1 = g_code[2*t], c2 = g_code[2*t+1];
  int s1 = c1 & (NTOK-1), s2 = c2 & (NTOK-1);
  float w1v = (s1 < ROWS_MAX) ? g_wgt[c1] : 0.f;
  float w2v = (s2 < ROWS_MAX) ? g_wgt[c2] : 0.f;
  size_t y1o = (s1 < ROWS_MAX) ? ((size_t)(c1>>13)*ROWS_MAX + s1)*EDIM : 0;
  size_t y2o = (s2 < ROWS_MAX) ? ((size_t)(c2>>13)*ROWS_MAX + s2)*EDIM : 0;
  const float4* xr = reinterpret_cast<const float4*>(x + (size_t)t*EDIM);
  const uint2* y1 = reinterpret_cast<const uint2*>(g_y16 + y1o);
  const uint2* y2 = reinterpret_cast<const uint2*>(g_y16 + y2o);
  float4* o = reinterpret_cast<float4*>(out + (size_t)t*EDIM);
  for (int j = threadIdx.x; j < EDIM/4; j += blockDim.x){
    float4 a = xr[j];
    uint2 u1 = y1[j], u2 = y2[j];
    float2 b0 = __half22float2(*reinterpret_cast<__half2*>(&u1.x));
    float2 b1 = __half22float2(*reinterpret_cast<__half2*>(&u1.y));
    float2 c0 = __half22float2(*reinterpret_cast<__half2*>(&u2.x));
    float2 c1f = __half22float2(*reinterpret_cast<__half2*>(&u2.y));
    float4 rr;
    rr.x = a.x + w1v*b0.x + w2v*c0.x;
    rr.y = a.y + w1v*b0.y + w2v*c0.y;
    rr.z = a.z + w1v*b1.x + w2v*c1f.x;
    rr.w = a.w + w1v*b1.y + w2v*c1f.y;
    o[j] = rr;
  }
}

// ---------------- launch ----------------
extern "C" void kernel_launch(void* const* d_in, const int* in_sizes, int n_in,
                              void* d_out, int out_size){
  const float* x  = (const float*)d_in[0];
  const float* gw = (const float*)d_in[1];
  const float* gb = (const float*)d_in[2];
  const float* tp = (const float*)d_in[3];
  const float* w1 = (const float*)d_in[4];
  const float* b1 = (const float*)d_in[5];
  const float* w2 = (const float*)d_in[6];
  const float* b2 = (const float*)d_in[7];
  float* out = (float*)d_out;

  cudaFuncSetAttribute(moe_gemm<1>, cudaFuncAttributeMaxDynamicSharedMemorySize, SMEM_TOTAL);
  cudaFuncSetAttribute(moe_gemm<2>, cudaFuncAttributeMaxDynamicSharedMemorySize, SMEM_TOTAL);

  convert_kernel<<<4096, 256>>>(w1, w2);              // idx 0 (weights + init)
  router_kernel<<<NTOK/8, 256>>>(x, gw, gb, tp);      // idx 1 (also emits x16)
  capacity_aux_kernel<<<NEXP+1, 256>>>(out, out_size);// idx 2
  dim3 grid(EDIM/256, NEXP*32);
  moe_gemm<1><<<grid, 256, SMEM_TOTAL>>>(b1);         // idx 3  <-- profiled
  moe_gemm<2><<<grid, 256, SMEM_TOTAL>>>(b2);         // idx 4
  combine_kernel<<<NTOK, 256>>>(x, out);              // idx 5
}

// round 15
// speedup vs baseline: 1.0387x; 1.0162x over previous
#include <cuda_runtime.h>
#include <cuda_fp16.h>
#include <cstdint>

#define NTOK   8192
#define EDIM   2048
#define NEXP   8
#define CAPACITY 2560
#define ROWS_MAX 4096
#define KC     64
#define NKC    (EDIM/KC)     // 32 K-chunks
#define RTR_BLKS (NTOK/8)    // 1024 router blocks

// ---------------- device scratch (no allocs allowed) ----------------
__device__ int    g_count[NEXP];
__device__ float  g_probSum[NEXP];
__device__ int    g_tok[NEXP*NTOK];
__device__ float  g_wgt[NEXP*NTOK];
__device__ int    g_pos[NEXP*NTOK];
__device__ int    g_code[NTOK*2];
__device__ unsigned char g_drop[NEXP*NTOK];
__device__ __half g_w16[(size_t)2*NEXP*EDIM*EDIM];        // 134 MB (w1|w2 fp16)
__device__ __half g_x16[(size_t)NTOK*EDIM];               // 33 MB
__device__ __half g_h16[(size_t)NEXP*ROWS_MAX*EDIM];      // 134 MB
__device__ __half g_y16[(size_t)NEXP*ROWS_MAX*EDIM];      // 134 MB (fp16 y)

// ---------------- helpers ----------------
__device__ __forceinline__ uint32_t smem_u32(const void* p){
  uint32_t a; asm("{ .reg .u64 t; cvta.to.shared.u64 t, %1; cvt.u32.u64 %0, t; }" : "=r"(a) : "l"(p));
  return a;
}
__device__ __forceinline__ void cpa16(uint32_t dst, const void* src){
  asm volatile("cp.async.cg.shared.global [%0], [%1], 16;" :: "r"(dst), "l"(src));
}

// ---------------- init counters ----------------
__global__ void init_kernel(){
  if (threadIdx.x < NEXP){ g_count[threadIdx.x] = 0; g_probSum[threadIdx.x] = 0.f; }
}

// ---------------- fused: router (blocks 0..1023) + convert w1,w2 (rest) ----------------
__global__ void router_convert_kernel(const float* __restrict__ x, const float* __restrict__ gw,
                                      const float* __restrict__ gb, const float* __restrict__ temp,
                                      const float* __restrict__ w1, const float* __restrict__ w2){
  if (blockIdx.x >= RTR_BLKS){
    const size_t NW = (size_t)NEXP*EDIM*EDIM;
    size_t nb = gridDim.x - RTR_BLKS;
    size_t i = (size_t)(blockIdx.x - RTR_BLKS)*blockDim.x + threadIdx.x;
    size_t stride = nb*blockDim.x;
    uint2* o1 = reinterpret_cast<uint2*>(g_w16);
    uint2* o2 = reinterpret_cast<uint2*>(g_w16 + NW);
    const float4* s1 = reinterpret_cast<const float4*>(w1);
    const float4* s2 = reinterpret_cast<const float4*>(w2);
    for (size_t j=i; j<NW/4; j+=stride){
      float4 v = s1[j];
      __half2 a = __floats2half2_rn(v.x,v.y), b = __floats2half2_rn(v.z,v.w);
      o1[j] = make_uint2(*(uint32_t*)&a, *(uint32_t*)&b);
      v = s2[j];
      a = __floats2half2_rn(v.x,v.y); b = __floats2half2_rn(v.z,v.w);
      o2[j] = make_uint2(*(uint32_t*)&a, *(uint32_t*)&b);
    }
    return;
  }
  int t = (int)((blockIdx.x*blockDim.x + threadIdx.x) >> 5);
  int lane = threadIdx.x & 31;
  const float* xr = x + (size_t)t * EDIM;
  __half* xo = g_x16 + (size_t)t * EDIM;
  float acc[8] = {0,0,0,0,0,0,0,0};
  for (int d = lane; d < EDIM; d += 32){
    float xv = xr[d];
    xo[d] = __float2half(xv);
    const float4* g4 = reinterpret_cast<const float4*>(gw + (size_t)d*NEXP);
    float4 ga = g4[0], gbv = g4[1];
    acc[0] += xv*ga.x;  acc[1] += xv*ga.y;  acc[2] += xv*ga.z;  acc[3] += xv*ga.w;
    acc[4] += xv*gbv.x; acc[5] += xv*gbv.y; acc[6] += xv*gbv.z; acc[7] += xv*gbv.w;
  }
  #pragma unroll
  for (int off=16; off; off>>=1)
    #pragma unroll
    for (int e=0;e<8;e++) acc[e] += __shfl_down_sync(0xffffffffu, acc[e], off);
  if (lane==0){
    float it = 1.0f / fabsf(temp[0]);
    float p[8]; float m = -1e30f;
    #pragma unroll
    for (int e=0;e<8;e++){ p[e] = (acc[e]+gb[e])*it; m = fmaxf(m, p[e]); }
    float s = 0.f;
    #pragma unroll
    for (int e=0;e<8;e++){ p[e] = expf(p[e]-m); s += p[e]; }
    float inv = 1.f/s;
    #pragma unroll
    for (int e=0;e<8;e++){ p[e] *= inv; atomicAdd(&g_probSum[e], p[e]); }
    int e0 = 0;
    #pragma unroll
    for (int e=1;e<8;e++) if (p[e] > p[e0]) e0 = e;
    int e1 = (e0==0) ? 1 : 0;
    #pragma unroll
    for (int e=0;e<8;e++) if (e!=e0 && p[e] > p[e1]) e1 = e;
    float rs = 1.f/(p[e0]+p[e1]);
    int s0 = atomicAdd(&g_count[e0], 1);
    g_tok[e0*NTOK+s0] = t; g_wgt[e0*NTOK+s0] = p[e0]*rs; g_pos[e0*NTOK+s0] = t*2;
    g_code[t*2+0] = e0*NTOK + s0;
    int s1 = atomicAdd(&g_count[e1], 1);
    g_tok[e1*NTOK+s1] = t; g_wgt[e1*NTOK+s1] = p[e1]*rs; g_pos[e1*NTOK+s1] = t*2+1;
    g_code[t*2+1] = e1*NTOK + s1;
  }
}

// ---------------- capacity filter + aux loss (fused) ----------------
__global__ void capacity_aux_kernel(float* __restrict__ out, int out_size){
  if (blockIdx.x == NEXP){
    if (threadIdx.x == 0){
      float sum = 0.f;
      for (int e=0;e<NEXP;e++) sum += g_probSum[e];
      float mean = sum / NEXP;
      float var = 0.f;
      for (int e=0;e<NEXP;e++){ float d = g_probSum[e]-mean; var += d*d; }
      var /= (NEXP-1);
      float cv = sqrtf(var) / (mean + 1e-10f);
      float bal = 0.f;
      for (int e=0;e<NEXP;e++)
        bal += (g_probSum[e]/(float)NTOK) * ((float)g_count[e]/(float)NTOK);
      bal *= (float)NEXP;
      if (out_size > NTOK*EDIM) out[(size_t)NTOK*EDIM] = bal + 0.01f*cv;
    }
    return;
  }
  int e = blockIdx.x;
  int cnt = g_count[e];
  if (cnt <= CAPACITY) return;
  for (int i = threadIdx.x; i < cnt; i += blockDim.x){
    float wi = g_wgt[e*NTOK+i]; int pi = g_pos[e*NTOK+i];
    int rank = 0;
    for (int j=0;j<cnt;j++){
      float wj = g_wgt[e*NTOK+j];
      if (wj > wi || (wj == wi && g_pos[e*NTOK+j] < pi)) rank++;
    }
    g_drop[e*NTOK+i] = (rank >= CAPACITY) ? 1 : 0;
  }
  __syncthreads();
  for (int i = threadIdx.x; i < cnt; i += blockDim.x)
    if (g_drop[e*NTOK+i]) g_wgt[e*NTOK+i] = 0.f;
}

// ---------------- fp16 mma.sync GEMM, 128Mx256Nx64K chunks (R11 config) ----------------
// 8 warps (2x4), warp tile 64x64, 1 CTA/SM, XOR-swizzled smem (conflict-free)
#define A_ST 16384
#define B_ST 32768
#define STAGE_BYTES (A_ST + B_ST)
#define NSTAGE 4
#define META_OFF (NSTAGE*STAGE_BYTES)       // 196608
#define SMEM_TOTAL (META_OFF + 768)

template<int MODE>
__device__ __forceinline__ void load_A(
    int kt, int slot, int tid, uint32_t sbase,
    const __half* __restrict__ Xg, const int* __restrict__ stok)
{
  int k0 = kt*KC;
  uint32_t ab = sbase + slot*STAGE_BYTES;
  #pragma unroll
  for (int i=0;i<4;i++){
    int idx = tid + i*256;
    int r = idx >> 3, ko = idx & 7;
    size_t grow = (MODE==1) ? (size_t)stok[r] : (size_t)r;
    const __half* src = Xg + grow*EDIM + k0 + ko*8;
    uint32_t dst = ab + (uint32_t)(r*128 + ((ko ^ (r&7))<<4));
    cpa16(dst, src);
  }
}
template<int HALF>
__device__ __forceinline__ void load_B(
    int kt, int slot, int tid, uint32_t sbase,
    const __half* __restrict__ Wb)
{
  int k0 = kt*KC;
  uint32_t bb = sbase + slot*STAGE_BYTES + A_ST;
  #pragma unroll
  for (int i=HALF*4;i<HALF*4+4;i++){
    int idx = tid + i*256;
    int kr = idx >> 5, no = idx & 31;
    const __half* src = Wb + (size_t)(k0+kr)*EDIM + no*8;
    uint32_t dst = bb + (uint32_t)(kr*512 + ((no ^ (kr&7))<<4));
    cpa16(dst, src);
  }
}

__device__ __forceinline__ void ks_step(
    uint32_t ab, uint32_t bb, int wm, int wn, int arow_lo, int ako_hi, int ks,
    float (&c)[4][8][4])
{
  uint32_t a[4][4], b[8][2];
  #pragma unroll
  for (int mf=0; mf<4; mf++){
    int row = wm*64 + mf*16 + arow_lo;
    int ko  = ks*2 + ako_hi;
    uint32_t addr = ab + (uint32_t)(row*128 + ((ko ^ (row&7))<<4));
    asm volatile("ldmatrix.sync.aligned.m8n8.x4.shared.b16 {%0,%1,%2,%3}, [%4];"
      : "=r"(a[mf][0]),"=r"(a[mf][1]),"=r"(a[mf][2]),"=r"(a[mf][3]) : "r"(addr));
  }
  #pragma unroll
  for (int p=0; p<4; p++){
    int kr = ks*16 + arow_lo;
    int no = wn*8 + p*2 + ako_hi;
    uint32_t addr = bb + (uint32_t)(kr*512 + ((no ^ (kr&7))<<4));
    asm volatile("ldmatrix.sync.aligned.m8n8.x4.trans.shared.b16 {%0,%1,%2,%3}, [%4];"
      : "=r"(b[2*p][0]),"=r"(b[2*p][1]),"=r"(b[2*p+1][0]),"=r"(b[2*p+1][1]) : "r"(addr));
  }
  #pragma unroll
  for (int mf=0; mf<4; mf++)
    #pragma unroll
    for (int nf=0; nf<8; nf++)
      asm volatile("mma.sync.aligned.m16n8k16.row.col.f32.f16.f16.f32 "
        "{%0,%1,%2,%3}, {%4,%5,%6,%7}, {%8,%9}, {%0,%1,%2,%3};"
        : "+f"(c[mf][nf][0]), "+f"(c[mf][nf][1]), "+f"(c[mf][nf][2]), "+f"(c[mf][nf][3])
        : "r"(a[mf][0]),"r"(a[mf][1]),"r"(a[mf][2]),"r"(a[mf][3]),
          "r"(b[nf][0]),"r"(b[nf][1]));
}

template<int MODE>
__global__ void __launch_bounds__(256,1) moe_gemm(
    const float* __restrict__ bias)
{
  int e  = blockIdx.y >> 5;
  int rb = blockIdx.y & 31;
  int cnt = g_count[e]; if (cnt > ROWS_MAX) cnt = ROWS_MAX;
  int row0 = rb * 128;
  if (row0 >= cnt) return;
  int rows = cnt - row0; if (rows > 128) rows = 128;
  int n0 = blockIdx.x * 256;

  extern __shared__ char smem[];
  uint32_t sbase = smem_u32(smem);
  int tid = threadIdx.x, warp = tid>>5, lane = tid&31;
  int* stok = (int*)(smem + META_OFF);

  if (tid < 128){
    int tkn = 0;
    if (MODE==1 && tid < rows) tkn = g_tok[e*NTOK + row0 + tid];
    stok[tid] = tkn;
  }
  __syncthreads();

  const __half* Xg = (MODE==1) ? g_x16 : (g_h16 + ((size_t)e*ROWS_MAX + row0)*EDIM);
  const __half* Wb = g_w16 + ((size_t)((MODE-1)*NEXP + e))*EDIM*EDIM + n0;

  float c[4][8][4];
  #pragma unroll
  for (int a=0;a<4;a++)
    #pragma unroll
    for (int b=0;b<8;b++)
      #pragma unroll
      for (int q=0;q<4;q++) c[a][b][q] = 0.f;

  int wm = warp & 1, wn = warp >> 1;   // 2x4 warp grid: 64(M) x 64(N) each

  #pragma unroll
  for (int p=0;p<3;p++){
    load_A<MODE>(p, p, tid, sbase, Xg, stok);
    load_B<0>(p, p, tid, sbase, Wb);
    load_B<1>(p, p, tid, sbase, Wb);
    asm volatile("cp.async.commit_group;" ::: "memory");
  }

  int arow_lo = (lane & 15);
  int ako_hi  = (lane >> 4);

  #pragma unroll 4
  for (int kt=0; kt<NKC-3; kt++){
    int slot = kt & 3;
    asm volatile("cp.async.wait_group 2;" ::: "memory");
    __syncthreads();
    uint32_t ab = sbase + slot*STAGE_BYTES;
    uint32_t bb = ab + A_ST;
    int nslot = (kt+3) & 3;
    ks_step(ab, bb, wm, wn, arow_lo, ako_hi, 0, c);
    load_A<MODE>(kt+3, nslot, tid, sbase, Xg, stok);
    ks_step(ab, bb, wm, wn, arow_lo, ako_hi, 1, c);
    load_B<0>(kt+3, nslot, tid, sbase, Wb);
    ks_step(ab, bb, wm, wn, arow_lo, ako_hi, 2, c);
    load_B<1>(kt+3, nslot, tid, sbase, Wb);
    ks_step(ab, bb, wm, wn, arow_lo, ako_hi, 3, c);
    asm volatile("cp.async.commit_group;" ::: "memory");
  }
  #pragma unroll
  for (int kt=NKC-3; kt<NKC; kt++){
    int slot = kt & 3;
    if      (kt == NKC-3) asm volatile("cp.async.wait_group 2;" ::: "memory");
    else if (kt == NKC-2) asm volatile("cp.async.wait_group 1;" ::: "memory");
    else                  asm volatile("cp.async.wait_group 0;" ::: "memory");
    __syncthreads();
    uint32_t ab = sbase + slot*STAGE_BYTES;
    uint32_t bb = ab + A_ST;
    #pragma unroll
    for (int ks=0; ks<4; ks++) ks_step(ab, bb, wm, wn, arow_lo, ako_hi, ks, c);
  }

  // ---------------- epilogue (registers -> gmem, fp16) ----------------
  int lr = lane>>2, lc = lane&3;
  const float* brow = bias + e*EDIM + n0 + wn*64;
  __half* ob = ((MODE==1) ? g_h16 : g_y16) + ((size_t)e*ROWS_MAX + row0)*EDIM + n0 + wn*64;
  #pragma unroll
  for (int nf=0; nf<8; nf++){
    int col = nf*8 + lc*2;
    float bv0 = brow[col], bv1 = brow[col+1];
    #pragma unroll
    for (int mf=0; mf<4; mf++){
      int r_ = wm*64 + mf*16 + lr;
      if (r_ < rows){
        float v0 = c[mf][nf][0]+bv0, v1 = c[mf][nf][1]+bv1;
        if (MODE==1){ v0 = fmaxf(v0,0.f); v1 = fmaxf(v1,0.f); }
        *reinterpret_cast<__half2*>(ob + (size_t)r_*EDIM + col) = __floats2half2_rn(v0, v1);
      }
      if (r_+8 < rows){
        float v0 = c[mf][nf][2]+bv0, v1 = c[mf][nf][3]+bv1;
        if (MODE==1){ v0 = fmaxf(v0,0.f); v1 = fmaxf(v1,0.f); }
        *reinterpret_cast<__half2*>(ob + (size_t)(r_+8)*EDIM + col) = __floats2half2_rn(v0, v1);
      }
    }
  }
}

// ---------------- combine: out = x + w0*y0 + w1*y1 (y in fp16) ----------------
__global__ void combine_kernel(const float* __restrict__ x, float* __restrict__ out){
  int t = blockIdx.x;
  int c1 = g_code[2*t], c2 = g_code[2*t+1];
  int s1 = c1 & (NTOK-1), s2 = c2 & (NTOK-1);
  float w1v = (s1 < ROWS_MAX) ? g_wgt[c1] : 0.f;
  float w2v = (s2 < ROWS_MAX) ? g_wgt[c2] : 0.f;
  size_t y1o = (s1 < ROWS_MAX) ? ((size_t)(c1>>13)*ROWS_MAX + s1)*EDIM : 0;
  size_t y2o = (s2 < ROWS_MAX) ? ((size_t)(c2>>13)*ROWS_MAX + s2)*EDIM : 0;
  const float4* xr = reinterpret_cast<const float4*>(x + (size_t)t*EDIM);
  const uint2* y1 = reinterpret_cast<const uint2*>(g_y16 + y1o);
  const uint2* y2 = reinterpret_cast<const uint2*>(g_y16 + y2o);
  float4* o = reinterpret_cast<float4*>(out + (size_t)t*EDIM);
  for (int j = threadIdx.x; j < EDIM/4; j += blockDim.x){
    float4 a = xr[j];
    uint2 u1 = y1[j], u2 = y2[j];
    float2 b0 = __half22float2(*reinterpret_cast<__half2*>(&u1.x));
    float2 b1 = __half22float2(*reinterpret_cast<__half2*>(&u1.y));
    float2 c0 = __half22float2(*reinterpret_cast<__half2*>(&u2.x));
    float2 c1f = __half22float2(*reinterpret_cast<__half2*>(&u2.y));
    float4 rr;
    rr.x = a.x + w1v*b0.x + w2v*c0.x;
    rr.y = a.y + w1v*b0.y + w2v*c0.y;
    rr.z = a.z + w1v*b1.x + w2v*c1f.x;
    rr.w = a.w + w1v*b1.y + w2v*c1f.y;
    o[j] = rr;
  }
}

// ---------------- launch ----------------
extern "C" void kernel_launch(void* const* d_in, const int* in_sizes, int n_in,
                              void* d_out, int out_size){
  const float* x  = (const float*)d_in[0];
  const float* gw = (const float*)d_in[1];
  const float* gb = (const float*)d_in[2];
  const float* tp = (const float*)d_in[3];
  const float* w1 = (const float*)d_in[4];
  const float* b1 = (const float*)d_in[5];
  const float* w2 = (const float*)d_in[6];
  const float* b2 = (const float*)d_in[7];
  float* out = (float*)d_out;

  cudaFuncSetAttribute(moe_gemm<1>, cudaFuncAttributeMaxDynamicSharedMemorySize, SMEM_TOTAL);
  cudaFuncSetAttribute(moe_gemm<2>, cudaFuncAttributeMaxDynamicSharedMemorySize, SMEM_TOTAL);

  init_kernel<<<1, 64>>>();                                        // idx 0
  router_convert_kernel<<<RTR_BLKS + 3072, 256>>>(x, gw, gb, tp, w1, w2); // idx 1
  capacity_aux_kernel<<<NEXP+1, 256>>>(out, out_size);             // idx 2
  dim3 grid(EDIM/256, NEXP*32);
  moe_gemm<1><<<grid, 256, SMEM_TOTAL>>>(b1);                      // idx 3  <-- profiled
  moe_gemm<2><<<grid, 256, SMEM_TOTAL>>>(b2);                      // idx 4
  combine_kernel<<<NTOK, 256>>>(x, out);                           // idx 5
}

// round 16
// speedup vs baseline: 1.0497x; 1.0106x over previous
#include <cuda_runtime.h>
#include <cuda_fp16.h>
#include <cstdint>

#define NTOK   8192
#define EDIM   2048
#define NEXP   8
#define CAPACITY 2560
#define ROWS_MAX 4096
#define KC     64
#define NKC    (EDIM/KC)     // 32 K-chunks
#define RTR_BLKS (NTOK/8)    // 1024 router blocks
#define GEMM_NY (NEXP*32)    // 256 gemm y-rows

// ---------------- device scratch (no allocs allowed; zero-initialized at load) ----------------
__device__ int    g_count[NEXP];
__device__ float  g_probSum[NEXP];
__device__ int    g_tok[NEXP*NTOK];
__device__ float  g_wgt[NEXP*NTOK];
__device__ int    g_pos[NEXP*NTOK];
__device__ int    g_code[NTOK*2];
__device__ unsigned char g_drop[NEXP*NTOK];
__device__ __half g_w16[(size_t)2*NEXP*EDIM*EDIM];        // 134 MB (w1|w2 fp16)
__device__ __half g_x16[(size_t)NTOK*EDIM];               // 33 MB
__device__ __half g_h16[(size_t)NEXP*ROWS_MAX*EDIM];      // 134 MB
__device__ __half g_y16[(size_t)NEXP*ROWS_MAX*EDIM];      // 134 MB (fp16 y)

// ---------------- helpers ----------------
__device__ __forceinline__ uint32_t smem_u32(const void* p){
  uint32_t a; asm("{ .reg .u64 t; cvta.to.shared.u64 t, %1; cvt.u32.u64 %0, t; }" : "=r"(a) : "l"(p));
  return a;
}
__device__ __forceinline__ void cpa16(uint32_t dst, const void* src){
  asm volatile("cp.async.cg.shared.global [%0], [%1], 16;" :: "r"(dst), "l"(src));
}

// ---------------- fused: router (blocks 0..1023) + convert w1,w2 (rest) ----------------
__global__ void router_convert_kernel(const float* __restrict__ x, const float* __restrict__ gw,
                                      const float* __restrict__ gb, const float* __restrict__ temp,
                                      const float* __restrict__ w1, const float* __restrict__ w2){
  if (blockIdx.x >= RTR_BLKS){
    const size_t NW = (size_t)NEXP*EDIM*EDIM;
    size_t nb = gridDim.x - RTR_BLKS;
    size_t i = (size_t)(blockIdx.x - RTR_BLKS)*blockDim.x + threadIdx.x;
    size_t stride = nb*blockDim.x;
    uint2* o1 = reinterpret_cast<uint2*>(g_w16);
    uint2* o2 = reinterpret_cast<uint2*>(g_w16 + NW);
    const float4* s1 = reinterpret_cast<const float4*>(w1);
    const float4* s2 = reinterpret_cast<const float4*>(w2);
    for (size_t j=i; j<NW/4; j+=stride){
      float4 v = s1[j];
      __half2 a = __floats2half2_rn(v.x,v.y), b = __floats2half2_rn(v.z,v.w);
      o1[j] = make_uint2(*(uint32_t*)&a, *(uint32_t*)&b);
      v = s2[j];
      a = __floats2half2_rn(v.x,v.y); b = __floats2half2_rn(v.z,v.w);
      o2[j] = make_uint2(*(uint32_t*)&a, *(uint32_t*)&b);
    }
    return;
  }
  int t = (int)((blockIdx.x*blockDim.x + threadIdx.x) >> 5);
  int lane = threadIdx.x & 31;
  const float* xr = x + (size_t)t * EDIM;
  __half* xo = g_x16 + (size_t)t * EDIM;
  float acc[8] = {0,0,0,0,0,0,0,0};
  for (int d = lane; d < EDIM; d += 32){
    float xv = xr[d];
    xo[d] = __float2half(xv);
    const float4* g4 = reinterpret_cast<const float4*>(gw + (size_t)d*NEXP);
    float4 ga = g4[0], gbv = g4[1];
    acc[0] += xv*ga.x;  acc[1] += xv*ga.y;  acc[2] += xv*ga.z;  acc[3] += xv*ga.w;
    acc[4] += xv*gbv.x; acc[5] += xv*gbv.y; acc[6] += xv*gbv.z; acc[7] += xv*gbv.w;
  }
  #pragma unroll
  for (int off=16; off; off>>=1)
    #pragma unroll
    for (int e=0;e<8;e++) acc[e] += __shfl_down_sync(0xffffffffu, acc[e], off);
  if (lane==0){
    float it = 1.0f / fabsf(temp[0]);
    float p[8]; float m = -1e30f;
    #pragma unroll
    for (int e=0;e<8;e++){ p[e] = (acc[e]+gb[e])*it; m = fmaxf(m, p[e]); }
    float s = 0.f;
    #pragma unroll
    for (int e=0;e<8;e++){ p[e] = expf(p[e]-m); s += p[e]; }
    float inv = 1.f/s;
    #pragma unroll
    for (int e=0;e<8;e++){ p[e] *= inv; atomicAdd(&g_probSum[e], p[e]); }
    int e0 = 0;
    #pragma unroll
    for (int e=1;e<8;e++) if (p[e] > p[e0]) e0 = e;
    int e1 = (e0==0) ? 1 : 0;
    #pragma unroll
    for (int e=0;e<8;e++) if (e!=e0 && p[e] > p[e1]) e1 = e;
    float rs = 1.f/(p[e0]+p[e1]);
    int s0 = atomicAdd(&g_count[e0], 1);
    g_tok[e0*NTOK+s0] = t; g_wgt[e0*NTOK+s0] = p[e0]*rs; g_pos[e0*NTOK+s0] = t*2;
    g_code[t*2+0] = e0*NTOK + s0;
    int s1 = atomicAdd(&g_count[e1], 1);
    g_tok[e1*NTOK+s1] = t; g_wgt[e1*NTOK+s1] = p[e1]*rs; g_pos[e1*NTOK+s1] = t*2+1;
    g_code[t*2+1] = e1*NTOK + s1;
  }
}

// ---------------- capacity + aux work (device fn, called from moe_gemm<1> extra blocks) ----------------
__device__ void capacity_aux_block(int cb, float* __restrict__ out, int out_size){
  if (cb == NEXP){
    if (threadIdx.x == 0){
      float sum = 0.f;
      for (int e=0;e<NEXP;e++) sum += g_probSum[e];
      float mean = sum / NEXP;
      float var = 0.f;
      for (int e=0;e<NEXP;e++){ float d = g_probSum[e]-mean; var += d*d; }
      var /= (NEXP-1);
      float cv = sqrtf(var) / (mean + 1e-10f);
      float bal = 0.f;
      for (int e=0;e<NEXP;e++)
        bal += (g_probSum[e]/(float)NTOK) * ((float)g_count[e]/(float)NTOK);
      bal *= (float)NEXP;
      if (out_size > NTOK*EDIM) out[(size_t)NTOK*EDIM] = bal + 0.01f*cv;
    }
    return;
  }
  int e = cb;
  int cnt = g_count[e];
  if (cnt <= CAPACITY) return;
  for (int i = threadIdx.x; i < cnt; i += blockDim.x){
    float wi = g_wgt[e*NTOK+i]; int pi = g_pos[e*NTOK+i];
    int rank = 0;
    for (int j=0;j<cnt;j++){
      float wj = g_wgt[e*NTOK+j];
      if (wj > wi || (wj == wi && g_pos[e*NTOK+j] < pi)) rank++;
    }
    g_drop[e*NTOK+i] = (rank >= CAPACITY) ? 1 : 0;
  }
  __syncthreads();
  for (int i = threadIdx.x; i < cnt; i += blockDim.x)
    if (g_drop[e*NTOK+i]) g_wgt[e*NTOK+i] = 0.f;
}

// ---------------- fp16 mma.sync GEMM, 128Mx256Nx64K chunks ----------------
// 8 warps (2x4), warp tile 64x64, 1 CTA/SM, XOR-swizzled smem (conflict-free)
#define A_ST 16384
#define B_ST 32768
#define STAGE_BYTES (A_ST + B_ST)
#define NSTAGE 4
#define META_OFF (NSTAGE*STAGE_BYTES)       // 196608
#define SMEM_TOTAL (META_OFF + 768)

template<int MODE>
__device__ __forceinline__ void load_A(
    int kt, int slot, int tid, uint32_t sbase,
    const __half* __restrict__ Xg, const int* __restrict__ stok)
{
  int k0 = kt*KC;
  uint32_t ab = sbase + slot*STAGE_BYTES;
  #pragma unroll
  for (int i=0;i<4;i++){
    int idx = tid + i*256;
    int r = idx >> 3, ko = idx & 7;
    size_t grow = (MODE==1) ? (size_t)stok[r] : (size_t)r;
    const __half* src = Xg + grow*EDIM + k0 + ko*8;
    uint32_t dst = ab + (uint32_t)(r*128 + ((ko ^ (r&7))<<4));
    cpa16(dst, src);
  }
}
template<int HALF>
__device__ __forceinline__ void load_B(
    int kt, int slot, int tid, uint32_t sbase,
    const __half* __restrict__ Wb)
{
  int k0 = kt*KC;
  uint32_t bb = sbase + slot*STAGE_BYTES + A_ST;
  #pragma unroll
  for (int i=HALF*4;i<HALF*4+4;i++){
    int idx = tid + i*256;
    int kr = idx >> 5, no = idx & 31;
    const __half* src = Wb + (size_t)(k0+kr)*EDIM + no*8;
    uint32_t dst = bb + (uint32_t)(kr*512 + ((no ^ (kr&7))<<4));
    cpa16(dst, src);
  }
}

__device__ __forceinline__ void ks_step(
    uint32_t ab, uint32_t bb, int wm, int wn, int arow_lo, int ako_hi, int ks,
    float (&c)[4][8][4])
{
  uint32_t a[4][4], b[8][2];
  #pragma unroll
  for (int mf=0; mf<4; mf++){
    int row = wm*64 + mf*16 + arow_lo;
    int ko  = ks*2 + ako_hi;
    uint32_t addr = ab + (uint32_t)(row*128 + ((ko ^ (row&7))<<4));
    asm volatile("ldmatrix.sync.aligned.m8n8.x4.shared.b16 {%0,%1,%2,%3}, [%4];"
      : "=r"(a[mf][0]),"=r"(a[mf][1]),"=r"(a[mf][2]),"=r"(a[mf][3]) : "r"(addr));
  }
  #pragma unroll
  for (int p=0; p<4; p++){
    int kr = ks*16 + arow_lo;
    int no = wn*8 + p*2 + ako_hi;
    uint32_t addr = bb + (uint32_t)(kr*512 + ((no ^ (kr&7))<<4));
    asm volatile("ldmatrix.sync.aligned.m8n8.x4.trans.shared.b16 {%0,%1,%2,%3}, [%4];"
      : "=r"(b[2*p][0]),"=r"(b[2*p][1]),"=r"(b[2*p+1][0]),"=r"(b[2*p+1][1]) : "r"(addr));
  }
  #pragma unroll
  for (int mf=0; mf<4; mf++)
    #pragma unroll
    for (int nf=0; nf<8; nf++)
      asm volatile("mma.sync.aligned.m16n8k16.row.col.f32.f16.f16.f32 "
        "{%0,%1,%2,%3}, {%4,%5,%6,%7}, {%8,%9}, {%0,%1,%2,%3};"
        : "+f"(c[mf][nf][0]), "+f"(c[mf][nf][1]), "+f"(c[mf][nf][2]), "+f"(c[mf][nf][3])
        : "r"(a[mf][0]),"r"(a[mf][1]),"r"(a[mf][2]),"r"(a[mf][3]),
          "r"(b[nf][0]),"r"(b[nf][1]));
}

// MODE1: y-rows [0,256) = GEMM1; y-rows [256,265) = capacity/aux (x==0 only)
template<int MODE>
__global__ void __launch_bounds__(256,1) moe_gemm(
    const float* __restrict__ bias, float* __restrict__ out, int out_size)
{
  if (MODE==1 && blockIdx.y >= GEMM_NY){
    if (blockIdx.x == 0) capacity_aux_block((int)(blockIdx.y - GEMM_NY), out, out_size);
    return;
  }
  int e  = blockIdx.y >> 5;
  int rb = blockIdx.y & 31;
  int cnt = g_count[e]; if (cnt > ROWS_MAX) cnt = ROWS_MAX;
  int row0 = rb * 128;
  if (row0 >= cnt) return;
  int rows = cnt - row0; if (rows > 128) rows = 128;
  int n0 = blockIdx.x * 256;

  extern __shared__ char smem[];
  uint32_t sbase = smem_u32(smem);
  int tid = threadIdx.x, warp = tid>>5, lane = tid&31;
  int* stok = (int*)(smem + META_OFF);

  if (tid < 128){
    int tkn = 0;
    if (MODE==1 && tid < rows) tkn = g_tok[e*NTOK + row0 + tid];
    stok[tid] = tkn;
  }
  __syncthreads();

  const __half* Xg = (MODE==1) ? g_x16 : (g_h16 + ((size_t)e*ROWS_MAX + row0)*EDIM);
  const __half* Wb = g_w16 + ((size_t)((MODE-1)*NEXP + e))*EDIM*EDIM + n0;

  float c[4][8][4];
  #pragma unroll
  for (int a=0;a<4;a++)
    #pragma unroll
    for (int b=0;b<8;b++)
      #pragma unroll
      for (int q=0;q<4;q++) c[a][b][q] = 0.f;

  int wm = warp & 1, wn = warp >> 1;   // 2x4 warp grid: 64(M) x 64(N) each

  #pragma unroll
  for (int p=0;p<3;p++){
    load_A<MODE>(p, p, tid, sbase, Xg, stok);
    load_B<0>(p, p, tid, sbase, Wb);
    load_B<1>(p, p, tid, sbase, Wb);
    asm volatile("cp.async.commit_group;" ::: "memory");
  }

  int arow_lo = (lane & 15);
  int ako_hi  = (lane >> 4);

  #pragma unroll 4
  for (int kt=0; kt<NKC-3; kt++){
    int slot = kt & 3;
    asm volatile("cp.async.wait_group 2;" ::: "memory");
    __syncthreads();
    uint32_t ab = sbase + slot*STAGE_BYTES;
    uint32_t bb = ab + A_ST;
    int nslot = (kt+3) & 3;
    ks_step(ab, bb, wm, wn, arow_lo, ako_hi, 0, c);
    load_A<MODE>(kt+3, nslot, tid, sbase, Xg, stok);
    ks_step(ab, bb, wm, wn, arow_lo, ako_hi, 1, c);
    load_B<0>(kt+3, nslot, tid, sbase, Wb);
    ks_step(ab, bb, wm, wn, arow_lo, ako_hi, 2, c);
    load_B<1>(kt+3, nslot, tid, sbase, Wb);
    ks_step(ab, bb, wm, wn, arow_lo, ako_hi, 3, c);
    asm volatile("cp.async.commit_group;" ::: "memory");
  }
  #pragma unroll
  for (int kt=NKC-3; kt<NKC; kt++){
    int slot = kt & 3;
    if      (kt == NKC-3) asm volatile("cp.async.wait_group 2;" ::: "memory");
    else if (kt == NKC-2) asm volatile("cp.async.wait_group 1;" ::: "memory");
    else                  asm volatile("cp.async.wait_group 0;" ::: "memory");
    __syncthreads();
    uint32_t ab = sbase + slot*STAGE_BYTES;
    uint32_t bb = ab + A_ST;
    #pragma unroll
    for (int ks=0; ks<4; ks++) ks_step(ab, bb, wm, wn, arow_lo, ako_hi, ks, c);
  }

  // ---------------- epilogue (registers -> gmem, fp16) ----------------
  int lr = lane>>2, lc = lane&3;
  const float* brow = bias + e*EDIM + n0 + wn*64;
  __half* ob = ((MODE==1) ? g_h16 : g_y16) + ((size_t)e*ROWS_MAX + row0)*EDIM + n0 + wn*64;
  #pragma unroll
  for (int nf=0; nf<8; nf++){
    int col = nf*8 + lc*2;
    float bv0 = brow[col], bv1 = brow[col+1];
    #pragma unroll
    for (int mf=0; mf<4; mf++){
      int r_ = wm*64 + mf*16 + lr;
      if (r_ < rows){
        float v0 = c[mf][nf][0]+bv0, v1 = c[mf][nf][1]+bv1;
        if (MODE==1){ v0 = fmaxf(v0,0.f); v1 = fmaxf(v1,0.f); }
        *reinterpret_cast<__half2*>(ob + (size_t)r_*EDIM + col) = __floats2half2_rn(v0, v1);
      }
      if (r_+8 < rows){
        float v0 = c[mf][nf][2]+bv0, v1 = c[mf][nf][3]+bv1;
        if (MODE==1){ v0 = fmaxf(v0,0.f); v1 = fmaxf(v1,0.f); }
        *reinterpret_cast<__half2*>(ob + (size_t)(r_+8)*EDIM + col) = __floats2half2_rn(v0, v1);
      }
    }
  }
}

// ---------------- combine: out = x + w0*y0 + w1*y1 (y in fp16); resets counters ----------------
__global__ void combine_kernel(const float* __restrict__ x, float* __restrict__ out){
  int t = blockIdx.x;
  // reset routing counters for the next graph replay (nothing after router reads them this run)
  if (t == 0 && threadIdx.x < NEXP){
    g_count[threadIdx.x] = 0; g_probSum[threadIdx.x] = 0.f;
  }
  int c1 = g_code[2*t], c2 = g_code[2*t+1];
  int s1 = c1 & (NTOK-1), s2 = c2 & (NTOK-1);
  float w1v = (s1 < ROWS_MAX) ? g_wgt[c1] : 0.f;
  float w2v = (s2 < ROWS_MAX) ? g_wgt[c2] : 0.f;
  size_t y1o = (s1 < ROWS_MAX) ? ((size_t)(c1>>13)*ROWS_MAX + s1)*EDIM : 0;
  size_t y2o = (s2 < ROWS_MAX) ? ((size_t)(c2>>13)*ROWS_MAX + s2)*EDIM : 0;
  const float4* xr = reinterpret_cast<const float4*>(x + (size_t)t*EDIM);
  const uint2* y1 = reinterpret_cast<const uint2*>(g_y16 + y1o);
  const uint2* y2 = reinterpret_cast<const uint2*>(g_y16 + y2o);
  float4* o = reinterpret_cast<float4*>(out + (size_t)t*EDIM);
  for (int j = threadIdx.x; j < EDIM/4; j += blockDim.x){
    float4 a = xr[j];
    uint2 u1 = y1[j], u2 = y2[j];
    float2 b0 = __half22float2(*reinterpret_cast<__half2*>(&u1.x));
    float2 b1 = __half22float2(*reinterpret_cast<__half2*>(&u1.y));
    float2 c0 = __half22float2(*reinterpret_cast<__half2*>(&u2.x));
    float2 c1f = __half22float2(*reinterpret_cast<__half2*>(&u2.y));
    float4 rr;
    rr.x = a.x + w1v*b0.x + w2v*c0.x;
    rr.y = a.y + w1v*b0.y + w2v*c0.y;
    rr.z = a.z + w1v*b1.x + w2v*c1f.x;
    rr.w = a.w + w1v*b1.y + w2v*c1f.y;
    o[j] = rr;
  }
}

// ---------------- launch ----------------
extern "C" void kernel_launch(void* const* d_in, const int* in_sizes, int n_in,
                              void* d_out, int out_size){
  const float* x  = (const float*)d_in[0];
  const float* gw = (const float*)d_in[1];
  const float* gb = (const float*)d_in[2];
  const float* tp = (const float*)d_in[3];
  const float* w1 = (const float*)d_in[4];
  const float* b1 = (const float*)d_in[5];
  const float* w2 = (const float*)d_in[6];
  const float* b2 = (const float*)d_in[7];
  float* out = (float*)d_out;

  cudaFuncSetAttribute(moe_gemm<1>, cudaFuncAttributeMaxDynamicSharedMemorySize, SMEM_TOTAL);
  cudaFuncSetAttribute(moe_gemm<2>, cudaFuncAttributeMaxDynamicSharedMemorySize, SMEM_TOTAL);

  router_convert_kernel<<<RTR_BLKS + 3072, 256>>>(x, gw, gb, tp, w1, w2); // idx 0
  dim3 grid1(EDIM/256, GEMM_NY + NEXP + 1);
  moe_gemm<1><<<grid1, 256, SMEM_TOTAL>>>(b1, out, out_size);             // idx 1 (+cap/aux)
  dim3 grid2(EDIM/256, GEMM_NY);
  moe_gemm<2><<<grid2, 256, SMEM_TOTAL>>>(b2, nullptr, 0);                // idx 2
  combine_kernel<<<NTOK, 256>>>(x, out);                                  // idx 3 <-- profiled (+reset)
}